// round 6
// baseline (speedup 1.0000x reference)
#include <cuda_runtime.h>
#include <cstdint>

#define BATCH 16
#define CH    128
#define HGT   128
#define WID   128
#define NTHR  256

#define NSTAGE 24            // 3 kh * 8 ci-chunks (16 ci each)
#define A_F    6144          // floats of A per stage (fragment-packed, 128 co)
#define B_CI_STRIDE 280      // floats per ci (2 rows of 136 + 8 pad)
#define B_ROW_OFF   136
#define SLOT_F (A_F + 16*B_CI_STRIDE)   // 10624 floats = 42496 B
#define SMEM_DYN (2*SLOT_F*4)           // 84992 B -> 1 CTA/SM

__device__ float g_x [(size_t)BATCH*CH*HGT*WID];
__device__ float g_xr[(size_t)BATCH*CH*HGT*WID];
__device__ float g_t [(size_t)BATCH*CH*HGT*WID];
__device__ float g_wp[2*24*6144];   // [set][stage][kw][k8][m16][lane][j]

// ---------- helpers ----------
__device__ __forceinline__ uint32_t smem_u32(const void* p){
    uint32_t a; asm("{ .reg .u64 t; cvta.to.shared.u64 t, %1; cvt.u32.u64 %0, t; }":"=r"(a):"l"(p));
    return a;
}
__device__ __forceinline__ float f2tf32(float f){
    uint32_t r; asm("cvt.rna.tf32.f32 %0, %1;":"=r"(r):"f"(f));
    return __uint_as_float(r);
}
__device__ __forceinline__ void cp16(uint32_t dst, const void* src, uint32_t ss){
    asm volatile("cp.async.cg.shared.global [%0], [%1], 16, %2;"
                 :: "r"(dst), "l"(src), "r"(ss) : "memory");
}
#define CP_COMMIT() asm volatile("cp.async.commit_group;":::"memory")
template<int N> __device__ __forceinline__ void cp_wait(){
    asm volatile("cp.async.wait_group %0;"::"n"(N):"memory");
}
__device__ __forceinline__ void mma8(float* d, const uint32_t* a, uint32_t b0, uint32_t b1){
    asm volatile("mma.sync.aligned.m16n8k8.row.col.f32.tf32.tf32.f32 "
        "{%0,%1,%2,%3}, {%4,%5,%6,%7}, {%8,%9}, {%0,%1,%2,%3};"
        : "+f"(d[0]), "+f"(d[1]), "+f"(d[2]), "+f"(d[3])
        : "r"(a[0]), "r"(a[1]), "r"(a[2]), "r"(a[3]), "r"(b0), "r"(b1));
}

// ---------- weight pack: per-lane MMA fragment layout, all 128 co ----------
__global__ void pack_w(const float* __restrict__ w1, const float* __restrict__ w2,
                       float* __restrict__ dst){
    int idx = blockIdx.x*blockDim.x + threadIdx.x;
    if (idx >= 2*147456) return;
    int r = idx;
    int set = r / 147456; r %= 147456;
    int s   = r / 6144;   r %= 6144;
    int kw  = r / 2048;   r %= 2048;
    int k8  = r / 1024;   r %= 1024;
    int m16 = r / 128;    r %= 128;
    int lane= r >> 2;
    int j   = r & 3;
    int g = lane>>2, t = lane&3;
    int co   = m16*16 + g + ((j&1)<<3);
    int kcol = t + ((j>>1)<<2);
    int kh = s>>3, chunk = s&7;
    int ci = chunk*16 + k8*8 + kcol;
    const float* w = set ? w2 : w1;
    dst[idx] = f2tf32(w[(size_t)co*(CH*9) + ci*9 + kh*3 + kw]);
}

// ---------- round pre-pass ----------
__global__ void round_x(const float4* __restrict__ in, float4* __restrict__ out, int n4){
    for (int i = blockIdx.x*blockDim.x + threadIdx.x; i < n4; i += gridDim.x*blockDim.x){
        float4 v = in[i];
        v.x = f2tf32(v.x); v.y = f2tf32(v.y); v.z = f2tf32(v.z); v.w = f2tf32(v.w);
        out[i] = v;
    }
}

// ---------- conv kernel ----------
// MODE 0: out = rna(relu(conv+b))
// MODE 1: v = xadd + (conv+b)/3 ; out = v ; out2 = rna(v)
// MODE 2: out = relu(xadd + (conv+b)/3)
template<int MODE>
__global__ void __launch_bounds__(NTHR, 1)
conv_mma(const float* __restrict__ in, const float* __restrict__ wp,
         const float* __restrict__ bias, const float* __restrict__ xadd,
         float* __restrict__ out, float* __restrict__ out2)
{
    extern __shared__ __align__(1024) float sm[];
    const int tid = threadIdx.x, lane = tid&31, wid = tid>>5;
    const int g = lane>>2, t = lane&3;
    const int wm = wid&1, wn = wid>>1;        // wm: 64-co half ; wn: 0..3
    const int brow = wn>>1, nb = (wn&1)*64;   // output row sel + px base
    const int h0 = blockIdx.x*2, b = blockIdx.y;
    const float* in_b = in + (size_t)b*CH*HGT*WID;

    float d[4][8][4];
#pragma unroll
    for (int mt=0;mt<4;mt++)
#pragma unroll
        for (int nt=0;nt<8;nt++)
#pragma unroll
            for (int c=0;c<4;c++) d[mt][nt][c] = 0.f;

    auto issue_stage = [&](int s, int slot){
        float* sl = sm + slot*SLOT_F;
        uint32_t base = smem_u32(sl);
        // A: fragment-packed, contiguous (24576 B = 1536 cp16)
        const float4* asrc = (const float4*)(wp + (size_t)s*A_F);
#pragma unroll
        for (int i=0;i<6;i++){
            int u = tid + i*256;
            cp16(base + u*16, asrc + u, 16);
        }
        // B: 16 ci x 2 rows x 128 floats = 1024 cp16
        const int kh = s>>3, chunk = s&7;
#pragma unroll
        for (int i=0;i<4;i++){
            int v = tid + i*256;
            int ci = v>>6, rem = v&63, row = rem>>5, cw = rem&31;
            int r = h0 + kh - 1 + row;
            uint32_t ss = ((unsigned)r < HGT) ? 16u : 0u;
            int rc = ((unsigned)r < HGT) ? r : 0;
            const float* src = in_b + ((size_t)(chunk*16+ci)*HGT + rc)*WID + cw*4;
            cp16(base + A_F*4 + ci*1120 + row*544 + 16 + cw*16, src, ss);
        }
        // halo edge zeros
        if (tid < 64){
            int ci = tid>>2, rem = tid&3, row = rem>>1;
            sl[A_F + ci*B_CI_STRIDE + row*B_ROW_OFF + ((rem&1)?132:3)] = 0.f;
        }
    };

    issue_stage(0, 0);
    CP_COMMIT();

    for (int s=0; s<NSTAGE; s++){
        if (s < NSTAGE-1){ issue_stage(s+1, (s+1)&1); CP_COMMIT(); cp_wait<1>(); }
        else             { cp_wait<0>(); }
        __syncthreads();

        const float* A  = sm + (s&1)*SLOT_F;
        const float* Bb = A + A_F;
#pragma unroll
        for (int kw=0; kw<3; kw++){
#pragma unroll
            for (int k8=0; k8<2; k8++){
                const int col = k8*8 + t;
                float4 av[4];
#pragma unroll
                for (int mt=0; mt<4; mt++)
                    av[mt] = *(const float4*)(A + ((kw*2+k8)*8 + wm*4+mt)*128 + lane*4);
                const float* bp = Bb + col*B_CI_STRIDE + brow*B_ROW_OFF + 3 + nb + g + kw;
#pragma unroll
                for (int nt=0; nt<8; nt++){
                    uint32_t b0 = __float_as_uint(bp[nt*8]);
                    uint32_t b1 = __float_as_uint(bp[nt*8 + 4*B_CI_STRIDE]);
#pragma unroll
                    for (int mt=0; mt<4; mt++)
                        mma8(d[mt][nt], (const uint32_t*)&av[mt], b0, b1);
                }
            }
        }
        __syncthreads();
    }

    // ---- epilogue ----
    const float inv3 = 1.0f/3.0f;
    const int h = h0 + brow;
#pragma unroll
    for (int mt=0; mt<4; mt++){
        const int co0 = wm*64 + mt*16 + g;
        const int co1 = co0 + 8;
        const float bv0 = bias[co0], bv1 = bias[co1];
        float* o0 = out + (((size_t)b*CH + co0)*HGT + h)*WID;
        float* o1 = out + (((size_t)b*CH + co1)*HGT + h)*WID;
        const float* x0 = (MODE!=0) ? xadd + (((size_t)b*CH + co0)*HGT + h)*WID : nullptr;
        const float* x1 = (MODE!=0) ? xadd + (((size_t)b*CH + co1)*HGT + h)*WID : nullptr;
        float* r0 = (MODE==1) ? out2 + (((size_t)b*CH + co0)*HGT + h)*WID : nullptr;
        float* r1 = (MODE==1) ? out2 + (((size_t)b*CH + co1)*HGT + h)*WID : nullptr;
#pragma unroll
        for (int nt=0; nt<8; nt++){
            const int n = nb + nt*8 + t*2;
            float v00 = d[mt][nt][0] + bv0, v01 = d[mt][nt][1] + bv0;
            float v10 = d[mt][nt][2] + bv1, v11 = d[mt][nt][3] + bv1;
            if (MODE == 0){
                v00 = f2tf32(fmaxf(v00, 0.f)); v01 = f2tf32(fmaxf(v01, 0.f));
                v10 = f2tf32(fmaxf(v10, 0.f)); v11 = f2tf32(fmaxf(v11, 0.f));
                *(float2*)(o0 + n) = make_float2(v00, v01);
                *(float2*)(o1 + n) = make_float2(v10, v11);
            } else {
                float2 xa = *(const float2*)(x0 + n);
                float2 xb = *(const float2*)(x1 + n);
                v00 = xa.x + inv3*v00; v01 = xa.y + inv3*v01;
                v10 = xb.x + inv3*v10; v11 = xb.y + inv3*v11;
                if (MODE == 2){
                    v00 = fmaxf(v00,0.f); v01 = fmaxf(v01,0.f);
                    v10 = fmaxf(v10,0.f); v11 = fmaxf(v11,0.f);
                }
                *(float2*)(o0 + n) = make_float2(v00, v01);
                *(float2*)(o1 + n) = make_float2(v10, v11);
                if (MODE == 1){
                    *(float2*)(r0 + n) = make_float2(f2tf32(v00), f2tf32(v01));
                    *(float2*)(r1 + n) = make_float2(f2tf32(v10), f2tf32(v11));
                }
            }
        }
    }
}

// ---------- launch ----------
extern "C" void kernel_launch(void* const* d_in, const int* in_sizes, int n_in,
                              void* d_out, int out_size)
{
    const float* x  = (const float*)d_in[0];
    const float* w1 = (const float*)d_in[1];
    const float* b1 = (const float*)d_in[2];
    const float* w2 = (const float*)d_in[3];
    const float* b2 = (const float*)d_in[4];
    float* out = (float*)d_out;

    float *gx, *gxr, *gt, *gwp;
    cudaGetSymbolAddress((void**)&gx,  g_x);
    cudaGetSymbolAddress((void**)&gxr, g_xr);
    cudaGetSymbolAddress((void**)&gt,  g_t);
    cudaGetSymbolAddress((void**)&gwp, g_wp);

    cudaFuncSetAttribute(conv_mma<0>, cudaFuncAttributeMaxDynamicSharedMemorySize, SMEM_DYN);
    cudaFuncSetAttribute(conv_mma<1>, cudaFuncAttributeMaxDynamicSharedMemorySize, SMEM_DYN);
    cudaFuncSetAttribute(conv_mma<2>, cudaFuncAttributeMaxDynamicSharedMemorySize, SMEM_DYN);

    pack_w<<<(2*147456 + 255)/256, 256>>>(w1, w2, gwp);
    round_x<<<4096, 256>>>((const float4*)x, (float4*)gxr, (int)((size_t)BATCH*CH*HGT*WID/4));

    const float* wp1 = gwp;
    const float* wp2 = gwp + 147456;
    dim3 grid(HGT/2, BATCH);

    conv_mma<0><<<grid, NTHR, SMEM_DYN>>>(gxr, wp1, b1, nullptr, gt,  nullptr);
    conv_mma<1><<<grid, NTHR, SMEM_DYN>>>(gt,  wp2, b2, x,       gx,  gxr);
    conv_mma<0><<<grid, NTHR, SMEM_DYN>>>(gxr, wp1, b1, nullptr, gt,  nullptr);
    conv_mma<1><<<grid, NTHR, SMEM_DYN>>>(gt,  wp2, b2, gx,      gx,  gxr);
    conv_mma<0><<<grid, NTHR, SMEM_DYN>>>(gxr, wp1, b1, nullptr, gt,  nullptr);
    conv_mma<2><<<grid, NTHR, SMEM_DYN>>>(gt,  wp2, b2, gx,      out, nullptr);
}

// round 7
// speedup vs baseline: 1.1137x; 1.1137x over previous
#include <cuda_runtime.h>
#include <cstdint>

#define BATCH 16
#define CH    128
#define HGT   128
#define WID   128
#define NTHR  256

#define NSTAGE 24            // 3 kh * 8 ci-chunks (16 ci each)
#define A_F    3072          // floats of A per stage (fragment-packed)
#define B_CI_STRIDE 280      // floats per ci (2 rows of 136 + 8 pad)
#define B_ROW_OFF   136
#define SLOT_F 7552          // 3072 + 16*280
#define SMEM_DYN (3*SLOT_F*4)   // 90624 B -> 2 CTAs/SM (181KB of 228KB)

__device__ float g_x [(size_t)BATCH*CH*HGT*WID];
__device__ float g_xr[(size_t)BATCH*CH*HGT*WID];
__device__ float g_t [(size_t)BATCH*CH*HGT*WID];
__device__ float g_wp[2*2*24*3072];   // [set][cohalf][stage][fragment-packed 3072]

// ---------- helpers ----------
__device__ __forceinline__ uint32_t smem_u32(const void* p){
    uint32_t a; asm("{ .reg .u64 t; cvta.to.shared.u64 t, %1; cvt.u32.u64 %0, t; }":"=r"(a):"l"(p));
    return a;
}
__device__ __forceinline__ float f2tf32(float f){
    uint32_t r; asm("cvt.rna.tf32.f32 %0, %1;":"=r"(r):"f"(f));
    return __uint_as_float(r);
}
__device__ __forceinline__ void cp16(uint32_t dst, const void* src, uint32_t ss){
    asm volatile("cp.async.cg.shared.global [%0], [%1], 16, %2;"
                 :: "r"(dst), "l"(src), "r"(ss) : "memory");
}
#define CP_COMMIT() asm volatile("cp.async.commit_group;":::"memory")
template<int N> __device__ __forceinline__ void cp_wait(){
    asm volatile("cp.async.wait_group %0;"::"n"(N):"memory");
}
__device__ __forceinline__ void mma8(float* d, const uint32_t* a, uint32_t b0, uint32_t b1){
    asm volatile("mma.sync.aligned.m16n8k8.row.col.f32.tf32.tf32.f32 "
        "{%0,%1,%2,%3}, {%4,%5,%6,%7}, {%8,%9}, {%0,%1,%2,%3};"
        : "+f"(d[0]), "+f"(d[1]), "+f"(d[2]), "+f"(d[3])
        : "r"(a[0]), "r"(a[1]), "r"(a[2]), "r"(a[3]), "r"(b0), "r"(b1));
}

// ---------- weight pack: per-lane MMA fragment layout ----------
// dst[((((set*2+ch)*24+s)*3+kw)*2+k8)*4+m16][lane][j] ; j=0..3 = a0..a3 of m16n8k8
__global__ void pack_w(const float* __restrict__ w1, const float* __restrict__ w2,
                       float* __restrict__ dst){
    int idx = blockIdx.x*blockDim.x + threadIdx.x;
    if (idx >= 2*147456) return;
    int r = idx;
    int set = r / 147456; r %= 147456;
    int ch  = r / 73728;  r %= 73728;
    int s   = r / 3072;   r %= 3072;
    int kw  = r / 1024;   r %= 1024;
    int k8  = r / 512;    r %= 512;
    int m16 = r / 128;    r %= 128;
    int lane= r >> 2;
    int j   = r & 3;
    int g = lane>>2, t = lane&3;
    int co   = ch*64 + m16*16 + g + ((j&1)<<3);
    int kcol = t + ((j>>1)<<2);
    int kh = s>>3, chunk = s&7;
    int ci = chunk*16 + k8*8 + kcol;
    const float* w = set ? w2 : w1;
    dst[idx] = f2tf32(w[(size_t)co*(CH*9) + ci*9 + kh*3 + kw]);
}

// ---------- round pre-pass ----------
__global__ void round_x(const float4* __restrict__ in, float4* __restrict__ out, int n4){
    for (int i = blockIdx.x*blockDim.x + threadIdx.x; i < n4; i += gridDim.x*blockDim.x){
        float4 v = in[i];
        v.x = f2tf32(v.x); v.y = f2tf32(v.y); v.z = f2tf32(v.z); v.w = f2tf32(v.w);
        out[i] = v;
    }
}

// ---------- conv kernel ----------
// MODE 0: out = rna(relu(conv+b))
// MODE 1: v = xadd + (conv+b)/3 ; out = v ; out2 = rna(v)
// MODE 2: out = relu(xadd + (conv+b)/3)
template<int MODE>
__global__ void __launch_bounds__(NTHR, 2)
conv_mma(const float* __restrict__ in, const float* __restrict__ wp,
         const float* __restrict__ bias, const float* __restrict__ xadd,
         float* __restrict__ out, float* __restrict__ out2)
{
    extern __shared__ __align__(1024) float sm[];
    const int tid = threadIdx.x, lane = tid&31, wid = tid>>5;
    const int g = lane>>2, t = lane&3;
    const int wm = wid&1, wn = wid>>1;        // wm: m-half of 64co ; wn: 0..3
    const int brow = wn>>1, nb = (wn&1)*64;   // output row sel + px base
    const int h0 = blockIdx.x*2, b = blockIdx.y, ch = blockIdx.z;
    const float* in_b = in + (size_t)b*CH*HGT*WID;
    const float* wpc  = wp + (size_t)ch*73728;

    float d[2][8][4];
#pragma unroll
    for (int mt=0;mt<2;mt++)
#pragma unroll
        for (int nt=0;nt<8;nt++)
#pragma unroll
            for (int c=0;c<4;c++) d[mt][nt][c] = 0.f;

    auto issue_stage = [&](int s, int slot){
        float* sl = sm + slot*SLOT_F;
        uint32_t base = smem_u32(sl);
        // A: fragment-packed, contiguous copy (12288 B = 768 cp16)
        const float4* asrc = (const float4*)(wpc + (size_t)s*A_F);
#pragma unroll
        for (int i=0;i<3;i++){
            int u = tid + i*256;
            cp16(base + u*16, asrc + u, 16);
        }
        // B: 16 ci x 2 rows x 128 floats = 1024 cp16 (4 per thread)
        const int kh = s>>3, chunk = s&7;
#pragma unroll
        for (int i=0;i<4;i++){
            int v = tid + i*256;
            int ci = v>>6, rem = v&63, row = rem>>5, cw = rem&31;
            int r = h0 + kh - 1 + row;
            uint32_t ss = ((unsigned)r < HGT) ? 16u : 0u;
            int rc = ((unsigned)r < HGT) ? r : 0;
            const float* src = in_b + ((size_t)(chunk*16+ci)*HGT + rc)*WID + cw*4;
            cp16(base + A_F*4 + ci*1120 + row*544 + 16 + cw*16, src, ss);
        }
        // halo edge floats (w=-1 at idx 3, w=128 at idx 132): always zero
        if (tid < 64){
            int ci = tid>>2, rem = tid&3, row = rem>>1;
            sl[A_F + ci*B_CI_STRIDE + row*B_ROW_OFF + ((rem&1)?132:3)] = 0.f;
        }
    };

    issue_stage(0, 0); CP_COMMIT();
    issue_stage(1, 1); CP_COMMIT();

    int slot = 0;
    for (int s=0; s<NSTAGE; s++){
        if (s < NSTAGE-2) cp_wait<1>(); else cp_wait<0>();
        __syncthreads();          // single barrier per stage (3-slot rotation)

        const float* A  = sm + slot*SLOT_F;
        const float* Bb = A + A_F;
#pragma unroll
        for (int kw=0; kw<3; kw++){
#pragma unroll
            for (int k8=0; k8<2; k8++){
                const int col = k8*8 + t;
                float4 av[2];
#pragma unroll
                for (int mt=0; mt<2; mt++)
                    av[mt] = *(const float4*)(A + ((kw*2+k8)*4 + wm*2+mt)*128 + lane*4);
                const float* bp = Bb + col*B_CI_STRIDE + brow*B_ROW_OFF + 3 + nb + g + kw;
#pragma unroll
                for (int nt=0; nt<8; nt++){
                    uint32_t b0 = __float_as_uint(bp[nt*8]);
                    uint32_t b1 = __float_as_uint(bp[nt*8 + 4*B_CI_STRIDE]);
                    mma8(d[0][nt], (const uint32_t*)&av[0], b0, b1);
                    mma8(d[1][nt], (const uint32_t*)&av[1], b0, b1);
                }
            }
        }

        if (s < NSTAGE-2){
            int nslot = slot+2; if (nslot >= 3) nslot -= 3;
            issue_stage(s+2, nslot);
            CP_COMMIT();
        }
        slot = (slot+1 == 3) ? 0 : slot+1;
    }

    // ---- epilogue ----
    const float inv3 = 1.0f/3.0f;
    const int h = h0 + brow;
#pragma unroll
    for (int mt=0; mt<2; mt++){
        const int co0 = ch*64 + wm*32 + mt*16 + g;
        const int co1 = co0 + 8;
        const float bv0 = bias[co0], bv1 = bias[co1];
        float* o0 = out + (((size_t)b*CH + co0)*HGT + h)*WID;
        float* o1 = out + (((size_t)b*CH + co1)*HGT + h)*WID;
        const float* x0 = (MODE!=0) ? xadd + (((size_t)b*CH + co0)*HGT + h)*WID : nullptr;
        const float* x1 = (MODE!=0) ? xadd + (((size_t)b*CH + co1)*HGT + h)*WID : nullptr;
        float* r0 = (MODE==1) ? out2 + (((size_t)b*CH + co0)*HGT + h)*WID : nullptr;
        float* r1 = (MODE==1) ? out2 + (((size_t)b*CH + co1)*HGT + h)*WID : nullptr;
#pragma unroll
        for (int nt=0; nt<8; nt++){
            const int n = nb + nt*8 + t*2;
            float v00 = d[mt][nt][0] + bv0, v01 = d[mt][nt][1] + bv0;
            float v10 = d[mt][nt][2] + bv1, v11 = d[mt][nt][3] + bv1;
            if (MODE == 0){
                v00 = f2tf32(fmaxf(v00, 0.f)); v01 = f2tf32(fmaxf(v01, 0.f));
                v10 = f2tf32(fmaxf(v10, 0.f)); v11 = f2tf32(fmaxf(v11, 0.f));
                *(float2*)(o0 + n) = make_float2(v00, v01);
                *(float2*)(o1 + n) = make_float2(v10, v11);
            } else {
                float2 xa = *(const float2*)(x0 + n);
                float2 xb = *(const float2*)(x1 + n);
                v00 = xa.x + inv3*v00; v01 = xa.y + inv3*v01;
                v10 = xb.x + inv3*v10; v11 = xb.y + inv3*v11;
                if (MODE == 2){
                    v00 = fmaxf(v00,0.f); v01 = fmaxf(v01,0.f);
                    v10 = fmaxf(v10,0.f); v11 = fmaxf(v11,0.f);
                }
                *(float2*)(o0 + n) = make_float2(v00, v01);
                *(float2*)(o1 + n) = make_float2(v10, v11);
                if (MODE == 1){
                    *(float2*)(r0 + n) = make_float2(f2tf32(v00), f2tf32(v01));
                    *(float2*)(r1 + n) = make_float2(f2tf32(v10), f2tf32(v11));
                }
            }
        }
    }
}

// ---------- launch ----------
extern "C" void kernel_launch(void* const* d_in, const int* in_sizes, int n_in,
                              void* d_out, int out_size)
{
    const float* x  = (const float*)d_in[0];
    const float* w1 = (const float*)d_in[1];
    const float* b1 = (const float*)d_in[2];
    const float* w2 = (const float*)d_in[3];
    const float* b2 = (const float*)d_in[4];
    float* out = (float*)d_out;

    float *gx, *gxr, *gt, *gwp;
    cudaGetSymbolAddress((void**)&gx,  g_x);
    cudaGetSymbolAddress((void**)&gxr, g_xr);
    cudaGetSymbolAddress((void**)&gt,  g_t);
    cudaGetSymbolAddress((void**)&gwp, g_wp);

    cudaFuncSetAttribute(conv_mma<0>, cudaFuncAttributeMaxDynamicSharedMemorySize, SMEM_DYN);
    cudaFuncSetAttribute(conv_mma<1>, cudaFuncAttributeMaxDynamicSharedMemorySize, SMEM_DYN);
    cudaFuncSetAttribute(conv_mma<2>, cudaFuncAttributeMaxDynamicSharedMemorySize, SMEM_DYN);

    pack_w<<<(2*147456 + 255)/256, 256>>>(w1, w2, gwp);
    round_x<<<4096, 256>>>((const float4*)x, (float4*)gxr, (int)((size_t)BATCH*CH*HGT*WID/4));

    const float* wp1 = gwp;
    const float* wp2 = gwp + 147456;
    dim3 grid(HGT/2, BATCH, 2);

    conv_mma<0><<<grid, NTHR, SMEM_DYN>>>(gxr, wp1, b1, nullptr, gt,  nullptr);
    conv_mma<1><<<grid, NTHR, SMEM_DYN>>>(gt,  wp2, b2, x,       gx,  gxr);
    conv_mma<0><<<grid, NTHR, SMEM_DYN>>>(gxr, wp1, b1, nullptr, gt,  nullptr);
    conv_mma<1><<<grid, NTHR, SMEM_DYN>>>(gt,  wp2, b2, gx,      gx,  gxr);
    conv_mma<0><<<grid, NTHR, SMEM_DYN>>>(gxr, wp1, b1, nullptr, gt,  nullptr);
    conv_mma<2><<<grid, NTHR, SMEM_DYN>>>(gt,  wp2, b2, gx,      out, nullptr);
}